// round 4
// baseline (speedup 1.0000x reference)
#include <cuda_runtime.h>

// DAGConstraintLayer: out = tree_min_project(sigmoid(x)) over (262144, 127) fp32.
// parent(i)=(i-1)/2, complete binary tree depth 7.
//
// sigmoid monotone => min(sig(a),sig(b)) = sig(min(a,b)): propagate min on raw x
// (FMNMX only), sigmoid applied elementwise in the store pass.
//
// R4: 3-stage cp.async pipeline, 16-row tiles, 8 CTAs/SM (2048 thr, full warp
// residency), 2 barriers/iter, ~2 iterations of prefetch slack.
//
// P2 mapping: 256 threads = 16 rows x 16 subgroups. Subgroup g handles the
// level-4 subtree rooted at node 15+g (7 nodes, register-chain DFS) plus the
// ancestor chain via redundant value-idempotent min writes (designated single
// writer per ancestor node; racing readers observe pre- or post-write values,
// which are equal under min).

#define NODES 127
#define ROWS_PER_TILE 16
#define THREADS 256
#define STAGES 3
#define TILE_FLOATS (ROWS_PER_TILE * NODES)   // 2032
#define TILE_F4 (TILE_FLOATS / 4)             // 508
#define SMEM_BYTES (STAGES * TILE_FLOATS * 4) // 24384 -> 8 CTAs/SM

__device__ __forceinline__ void cp_async16(void* smem_dst, const void* gmem_src) {
    unsigned s = (unsigned)__cvta_generic_to_shared(smem_dst);
    asm volatile("cp.async.cg.shared.global [%0], [%1], 16;\n" :: "r"(s), "l"(gmem_src));
}
__device__ __forceinline__ void cp_commit() {
    asm volatile("cp.async.commit_group;\n" ::: "memory");
}
template <int N>
__device__ __forceinline__ void cp_wait() {
    asm volatile("cp.async.wait_group %0;\n" :: "n"(N) : "memory");
}

__device__ __forceinline__ float fast_sigmoid(float v) {
    return __fdividef(1.0f, 1.0f + __expf(-v));  // MUFU.EX2 + MUFU.RCP
}

// Register-chain DFS: path-min rides in a register (no LDS-after-STS dependence).
template <int I, int REM>
__device__ __forceinline__ void dfs_min(float* __restrict__ r, float pmin) {
    float v = fminf(r[I], pmin);
    r[I] = v;
    if constexpr (REM > 0) {
        dfs_min<2 * I + 1, REM - 1>(r, v);
        dfs_min<2 * I + 2, REM - 1>(r, v);
    }
}

extern __shared__ float smem[];  // 3 tile buffers

__device__ __forceinline__ void prefetch_tile(const float* __restrict__ x,
                                              float* buf, int t, int tid) {
    const float4* __restrict__ src = (const float4*)(x + (size_t)t * TILE_FLOATS);
    float4* dst = (float4*)buf;
    #pragma unroll
    for (int j = tid; j < TILE_F4; j += THREADS) cp_async16(dst + j, src + j);
}

__global__ void __launch_bounds__(THREADS, 8)
dag_constraint_kernel(const float* __restrict__ x, float* __restrict__ out,
                      int ntiles) {
    const int tid = threadIdx.x;
    const int G = gridDim.x;
    const int t0 = blockIdx.x;

    float* buf[STAGES] = { smem, smem + TILE_FLOATS, smem + 2 * TILE_FLOATS };

    // Prologue: two groups in flight.
    if (t0 < ntiles) prefetch_tile(x, buf[0], t0, tid);
    cp_commit();
    if (t0 + G < ntiles) prefetch_tile(x, buf[1], t0 + G, tid);
    cp_commit();

    int stage = 0;
    for (int t = t0; t < ntiles; t += G) {
        cp_wait<1>();        // group for tile t retired (in-order)
        __syncthreads();     // data visible; also fences prior iter's P3 reads

        // Prefetch t+2G into the buffer freed by iter-1's P3 (barrier above
        // guarantees all its readers are done).
        const int nxt2 = t + 2 * G;
        const int pstage = stage + 2 >= STAGES ? stage + 2 - STAGES : stage + 2;
        if (nxt2 < ntiles) prefetch_tile(x, buf[pstage], nxt2, tid);
        cp_commit();         // always commit (empty groups keep counting uniform)

        float* cur = buf[stage];

        // ---- P2: raw min-propagation ----
        {
            const int row = tid & 15;
            const int sg  = tid >> 4;            // 0..15, uniform per half-warp
            float* r = cur + row * NODES;        // odd stride: conflict-free

            const float v0 = r[0];                       // node 0 read-only
            const float v1 = fminf(r[1 + (sg >> 3)], v0);
            if ((sg & 7) == 0) r[1 + (sg >> 3)] = v1;    // nodes 1,2
            const float v2 = fminf(r[3 + (sg >> 2)], v1);
            if ((sg & 3) == 0) r[3 + (sg >> 2)] = v2;    // nodes 3..6
            const float v3 = fminf(r[7 + (sg >> 1)], v2);
            if ((sg & 1) == 0) r[7 + (sg >> 1)] = v3;    // nodes 7..14
            switch (sg) {                                // 7-node subtrees, lvls 4..6
                case 0:  dfs_min<15, 2>(r, v3); break;
                case 1:  dfs_min<16, 2>(r, v3); break;
                case 2:  dfs_min<17, 2>(r, v3); break;
                case 3:  dfs_min<18, 2>(r, v3); break;
                case 4:  dfs_min<19, 2>(r, v3); break;
                case 5:  dfs_min<20, 2>(r, v3); break;
                case 6:  dfs_min<21, 2>(r, v3); break;
                case 7:  dfs_min<22, 2>(r, v3); break;
                case 8:  dfs_min<23, 2>(r, v3); break;
                case 9:  dfs_min<24, 2>(r, v3); break;
                case 10: dfs_min<25, 2>(r, v3); break;
                case 11: dfs_min<26, 2>(r, v3); break;
                case 12: dfs_min<27, 2>(r, v3); break;
                case 13: dfs_min<28, 2>(r, v3); break;
                case 14: dfs_min<29, 2>(r, v3); break;
                case 15: dfs_min<30, 2>(r, v3); break;
            }
        }
        __syncthreads();

        // ---- P3: sigmoid + coalesced streaming store ----
        {
            const float4* s4 = (const float4*)cur;
            float4* __restrict__ gout = (float4*)(out + (size_t)t * TILE_FLOATS);
            #pragma unroll
            for (int j = tid; j < TILE_F4; j += THREADS) {
                float4 v = s4[j];
                v.x = fast_sigmoid(v.x);
                v.y = fast_sigmoid(v.y);
                v.z = fast_sigmoid(v.z);
                v.w = fast_sigmoid(v.w);
                __stcs(gout + j, v);
            }
        }
        // No barrier here: next iteration's post-wait barrier protects buffers.
        stage = stage + 1 >= STAGES ? 0 : stage + 1;
    }
}

extern "C" void kernel_launch(void* const* d_in, const int* in_sizes, int n_in,
                              void* d_out, int out_size) {
    const float* x = (const float*)d_in[0];
    float* out = (float*)d_out;

    const int total = in_sizes[0];              // 262144 * 127
    const int rows = total / NODES;             // 262144
    const int ntiles = rows / ROWS_PER_TILE;    // 16384

    int grid = 148 * 8;                         // persistent: 8 CTAs/SM
    if (grid > ntiles) grid = ntiles;

    dag_constraint_kernel<<<grid, THREADS, SMEM_BYTES>>>(x, out, ntiles);
}

// round 5
// speedup vs baseline: 1.0491x; 1.0491x over previous
#include <cuda_runtime.h>

// DAGConstraintLayer: out = tree_min_project(sigmoid(x)) over (262144, 127) fp32.
// parent(i)=(i-1)/2, complete binary tree depth 7.
//
// sigmoid monotone => min(sig(a),sig(b)) = sig(min(a,b)): propagate min on raw x
// (FMNMX only), sigmoid applied once per element in the store pass.
//
// R5: one __syncthreads per iteration.
//  - 32-row tiles (16256 B), 3-stage cp.async ring -> prefetch t+2G issued right
//    after the single barrier; reads stay in flight through compute.
//  - Warp owns 4 contiguous rows (2032 B, 16B aligned). P2 and P3 are warp-local:
//    P2 -> __syncwarp -> P3 (coalesced float4 sigmoid+store). No block-wide
//    P2/P3 barriers.
//  - P2 is divergence-free: every lane runs the same level-by-level sequence
//    with register-valued node indices (sub = lane>>2 picks one of 8 level-3
//    subtrees; row = lane&3). Shared-ancestor handling: all lanes of a row read
//    the ancestor in one lockstep LDS (pre-write value), compute the min
//    themselves, designated lane stores - deterministic, no race ambiguity.

#define NODES 127
#define ROWS_PER_TILE 32
#define ROWS_PER_WARP 4
#define THREADS 256
#define STAGES 3
#define TILE_FLOATS (ROWS_PER_TILE * NODES)    // 4064
#define TILE_F4 (TILE_FLOATS / 4)              // 1016
#define WARP_FLOATS (ROWS_PER_WARP * NODES)    // 508
#define WARP_F4 (WARP_FLOATS / 4)              // 127
#define SMEM_BYTES (STAGES * TILE_FLOATS * 4)  // 48768 (< 49152 default)

__device__ __forceinline__ void cp_async16(void* smem_dst, const void* gmem_src) {
    unsigned s = (unsigned)__cvta_generic_to_shared(smem_dst);
    asm volatile("cp.async.cg.shared.global [%0], [%1], 16;\n" :: "r"(s), "l"(gmem_src));
}
__device__ __forceinline__ void cp_commit() {
    asm volatile("cp.async.commit_group;\n" ::: "memory");
}
template <int N>
__device__ __forceinline__ void cp_wait() {
    asm volatile("cp.async.wait_group %0;\n" :: "n"(N) : "memory");
}

__device__ __forceinline__ float fast_sigmoid(float v) {
    return __fdividef(1.0f, 1.0f + __expf(-v));  // MUFU.EX2 + MUFU.RCP
}

extern __shared__ float smem[];  // 3 tile buffers

__device__ __forceinline__ void prefetch_tile(const float* __restrict__ x,
                                              float* buf, int t, int tid) {
    const float4* __restrict__ src = (const float4*)(x + (size_t)t * TILE_FLOATS);
    float4* dst = (float4*)buf;
    #pragma unroll
    for (int j = tid; j < TILE_F4; j += THREADS) cp_async16(dst + j, src + j);
}

__global__ void __launch_bounds__(THREADS)
dag_constraint_kernel(const float* __restrict__ x, float* __restrict__ out,
                      int ntiles) {
    const int tid  = threadIdx.x;
    const int warp = tid >> 5;
    const int lane = tid & 31;
    const int G    = gridDim.x;
    const int t0   = blockIdx.x;

    float* buf[STAGES] = { smem, smem + TILE_FLOATS, smem + 2 * TILE_FLOATS };

    // Prologue: two tiles in flight.
    if (t0 < ntiles) prefetch_tile(x, buf[0], t0, tid);
    cp_commit();
    if (t0 + G < ntiles) prefetch_tile(x, buf[1], t0 + G, tid);
    cp_commit();

    // P2 lane mapping (loop-invariant).
    const int row = lane & 3;          // row within warp's 4-row slice
    const int sub = lane >> 2;         // 0..7: level-3 subtree id
    const int n1 = 1 + (sub >> 2);     // node 1 or 2
    const int n2 = 3 + (sub >> 1);     // nodes 3..6
    const int n3 = 7 + sub;            // nodes 7..14 (unique per lane-group)
    const int b4 = 15 + 2 * sub;       // level-4 pair
    const int b5 = 31 + 4 * sub;       // level-5 quad
    const int b6 = 63 + 8 * sub;       // level-6 octet
    const int rowbase = (warp * ROWS_PER_WARP + row) * NODES;

    int stage = 0;
    for (int t = t0; t < ntiles; t += G) {
        cp_wait<1>();        // tile t retired (groups complete in order)
        __syncthreads();     // cross-thread visibility; also: every thread has
                             // finished iter t-1 entirely (frees buf[stage+2])

        // Prefetch t+2G into the now-free buffer; in flight through P2+P3.
        const int pf = t + 2 * G;
        const int ps = stage + 2 >= STAGES ? stage + 2 - STAGES : stage + 2;
        if (pf < ntiles) prefetch_tile(x, buf[ps], pf, tid);
        cp_commit();         // uniform group counting even when empty

        float* cur = buf[stage];
        float* r = cur + rowbase;

        // ---- P2: divergence-free min-propagation on raw x ----
        {
            const float v0 = r[0];                       // node 0: read-only
            const float v1 = fminf(r[n1], v0);           // lockstep read-before-
            if ((sub & 3) == 0) r[n1] = v1;              //   designated write
            const float v2 = fminf(r[n2], v1);
            if ((sub & 1) == 0) r[n2] = v2;
            const float v3 = fminf(r[n3], v2);
            r[n3] = v3;
            const float a0 = fminf(r[b4 + 0], v3); r[b4 + 0] = a0;
            const float a1 = fminf(r[b4 + 1], v3); r[b4 + 1] = a1;
            const float c0 = fminf(r[b5 + 0], a0); r[b5 + 0] = c0;
            const float c1 = fminf(r[b5 + 1], a0); r[b5 + 1] = c1;
            const float c2 = fminf(r[b5 + 2], a1); r[b5 + 2] = c2;
            const float c3 = fminf(r[b5 + 3], a1); r[b5 + 3] = c3;
            r[b6 + 0] = fminf(r[b6 + 0], c0);
            r[b6 + 1] = fminf(r[b6 + 1], c0);
            r[b6 + 2] = fminf(r[b6 + 2], c1);
            r[b6 + 3] = fminf(r[b6 + 3], c1);
            r[b6 + 4] = fminf(r[b6 + 4], c2);
            r[b6 + 5] = fminf(r[b6 + 5], c2);
            r[b6 + 6] = fminf(r[b6 + 6], c3);
            r[b6 + 7] = fminf(r[b6 + 7], c3);
        }
        __syncwarp();        // warp-local P2 -> P3 ordering (rows are warp-owned)

        // ---- P3: sigmoid + coalesced streaming store (warp's own slice) ----
        {
            const float4* s4 = (const float4*)(cur + warp * WARP_FLOATS);
            float4* __restrict__ gout =
                (float4*)(out + (size_t)t * TILE_FLOATS + warp * WARP_FLOATS);
            #pragma unroll
            for (int j = lane; j < WARP_F4; j += 32) {
                float4 v = s4[j];
                v.x = fast_sigmoid(v.x);
                v.y = fast_sigmoid(v.y);
                v.z = fast_sigmoid(v.z);
                v.w = fast_sigmoid(v.w);
                __stcs(gout + j, v);
            }
        }
        stage = stage + 1 >= STAGES ? 0 : stage + 1;
    }
}

extern "C" void kernel_launch(void* const* d_in, const int* in_sizes, int n_in,
                              void* d_out, int out_size) {
    const float* x = (const float*)d_in[0];
    float* out = (float*)d_out;

    const int total = in_sizes[0];              // 262144 * 127
    const int rows = total / NODES;             // 262144
    const int ntiles = rows / ROWS_PER_TILE;    // 8192

    int grid = 148 * 7;                         // persistent grid
    if (grid > ntiles) grid = ntiles;

    dag_constraint_kernel<<<grid, THREADS, SMEM_BYTES>>>(x, out, ntiles);
}